// round 14
// baseline (speedup 1.0000x reference)
#include <cuda_runtime.h>
#include <cstdint>

#define TT     224
#define HH     128
#define BB     64
#define SS     20
#define NN     1280      // BB*SS
#define GM     4         // sequences per LSTM CTA
#define NGRP   320       // NN/GM
#define NINTER 64
#define KSPLIT 8
#define TM     32        // seq tile in feats GEMM
#define TCHUNK 28        // 224/KSPLIT timesteps per k-split

#define NP2S   27        // weight k-quads resident in smem
#define NP2R   5         // weight k-quads resident in registers

typedef unsigned long long u64;

// ---------------- scratch (static device globals; no runtime allocation) ---------
__device__ __align__(16) float g_hs[(size_t)NN * TT * HH];   // [n][t][h]
__device__ int   g_len[NN];
__device__ int   g_order[NN];
__device__ __align__(16) float g_Wk[512 * 128];              // [p2][r] float4: W[r][4p2..4p2+3]
__device__ __align__(16) float g_psum[(size_t)KSPLIT * NN * NINTER];

// ---------------- helpers ----------------
__device__ __forceinline__ u64 ffma2(u64 a, u64 b, u64 c) {
    u64 d;
    asm("fma.rn.f32x2 %0, %1, %2, %3;" : "=l"(d) : "l"(a), "l"(b), "l"(c));
    return d;
}
__device__ __forceinline__ float f2lo(u64 v) { return __uint_as_float((unsigned)(v & 0xffffffffull)); }
__device__ __forceinline__ float f2hi(u64 v) { return __uint_as_float((unsigned)(v >> 32)); }
__device__ __forceinline__ float sigf(float v) {
    return __fdividef(1.0f, 1.0f + __expf(-v));
}
__device__ __forceinline__ float tanh_(float v) {
    float e = __expf(-2.0f * v);
    return __fdividef(1.0f - e, 1.0f + e);
}

// ---------------- kernel 1: ragged lengths ---------------------------------------
__global__ void k_lens(const float* __restrict__ x) {
    int n = blockIdx.x;
    const float* xs = x + (size_t)n * TT;
    int first = 1 << 30;
    for (int t = threadIdx.x; t < TT; t += 32)
        if (xs[t] == 0.0f) first = min(first, t);
    #pragma unroll
    for (int o = 16; o; o >>= 1)
        first = min(first, __shfl_xor_sync(0xffffffffu, first, o));
    if (threadIdx.x == 0)
        g_len[n] = (first == 0 || first >= TT) ? TT : (first + 1);
}

// ---------------- kernel 2: single-CTA counting sort by length -------------------
__global__ void __launch_bounds__(256) k_sort() {
    __shared__ int hist[256];
    __shared__ int off[256];
    int tid = threadIdx.x;
    hist[tid] = 0;
    __syncthreads();
    for (int n = tid; n < NN; n += 256) atomicAdd(&hist[g_len[n]], 1);
    __syncthreads();
    if (tid == 0) {
        int acc = 0;
        for (int i = 0; i < 256; i++) { off[i] = acc; acc += hist[i]; }
    }
    __syncthreads();
    for (int n = tid; n < NN; n += 256) {
        int pos = atomicAdd(&off[g_len[n]], 1);
        g_order[pos] = n;
    }
}

// ---------------- kernel 3: repack W_hh: g_Wk[p2*512 + r] = W[r][4p2..4p2+3] -----
__global__ void k_wt(const float* __restrict__ Whh) {
    int i = blockIdx.x * blockDim.x + threadIdx.x;   // 0..16383
    int r  = i & 511;
    int p2 = i >> 9;
    float4 v = ((const float4*)Whh)[r * 32 + p2];
    ((float4*)g_Wk)[p2 * 512 + r] = v;
}

// ---------------- kernel 4: LSTM (256 threads, gate-local layout) ----------------
// tid: u = tid>>1 (hidden unit), sh = tid&1 (sequence half).
// Thread owns ALL 4 gate rows of unit u (r_g = g*128+u) for seqs m0=2sh, m1=2sh+1.
// It therefore computes its 2 cells entirely locally: no gate exchange, no spre,
// ONE barrier per timestep (double-buffered h).
// Adjacent lanes (same u, different sh) share weight addresses -> pair-broadcast,
// weight LDS = 2 wavefronts per row per quad. h loads ~1 wf per quad per seq-pair.
// dynamic smem:
//   [0, 221184)        sW  : float4[27*512]     weight k-quads p2=0..26
//   [221184, 225280)   shf : float[2][4][128]   double-buffered h [buf][seq][unit]
//   [225280, 228864)   sx  : float[4][224]
#define LSTM_SMEM 228864
__global__ void __launch_bounds__(256, 1) k_lstm(
    const float* __restrict__ x, const float* __restrict__ Wih,
    const float* __restrict__ bih, const float* __restrict__ bhh)
{
    extern __shared__ __align__(16) char dyn[];
    ulonglong2* sW = (ulonglong2*)dyn;
    float* shf = (float*)(dyn + 221184);
    float* sx  = (float*)(dyn + 225280);
    __shared__ int sn[GM], sl[GM];

    int tid = threadIdx.x;
    int u  = tid >> 1;
    int sh = tid & 1;
    int m0 = 2 * sh, m1 = m0 + 1;

    int grp = (NGRP - 1) - blockIdx.x;   // longest groups scheduled first
    if (tid < GM) {
        int n = g_order[grp * GM + tid];
        sn[tid] = n;
        sl[tid] = g_len[n];
    }

    // stage smem weights (p2 = 0..26)
    const float4* Wk4 = (const float4*)g_Wk;
    float4* sW4 = (float4*)sW;
    for (int i = tid; i < NP2S * 512; i += 256) sW4[i] = Wk4[i];
    // zero both h buffers
    for (int i = tid; i < 1024; i += 256) shf[i] = 0.0f;

    // register weights (p2 = 27..31), all 4 gate rows of unit u
    ulonglong2 wr[NP2R][4];
    const ulonglong2* Wk2 = (const ulonglong2*)g_Wk;
    #pragma unroll
    for (int i = 0; i < NP2R; i++)
        #pragma unroll
        for (int g = 0; g < 4; g++)
            wr[i][g] = Wk2[(size_t)(NP2S + i) * 512 + g * 128 + u];

    float wi[4], bs[4];
    #pragma unroll
    for (int g = 0; g < 4; g++) {
        int r = g * 128 + u;
        wi[g] = Wih[r];
        bs[g] = bih[r] + bhh[r];
    }

    __syncthreads();
    int maxlen = max(max(sl[0], sl[1]), max(sl[2], sl[3]));
    int lenA = sl[m0], lenB = sl[m1];

    #pragma unroll
    for (int m = 0; m < GM; m++)
        for (int t = tid; t < TT; t += 256) sx[m * TT + t] = x[(size_t)sn[m] * TT + t];

    float* hsA = g_hs + (size_t)sn[m0] * TT * HH + u;
    float* hsB = g_hs + (size_t)sn[m1] * TT * HH + u;
    float cA = 0.0f, cB = 0.0f;
    __syncthreads();

    for (int t = 0; t < maxlen; t++) {
        int cur = t & 1, nxt = cur ^ 1;
        const ulonglong2* hb = (const ulonglong2*)(shf + cur * 512);

        // accumulators: [gate][seq m0/m1]
        u64 A0a = 0, A1a = 0, A2a = 0, A3a = 0;
        u64 A0b = 0, A1b = 0, A2b = 0, A3b = 0;

        #pragma unroll
        for (int p2 = 0; p2 < NP2S; p2++) {
            ulonglong2 hA = hb[m0 * 32 + p2];
            ulonglong2 hB = hb[m1 * 32 + p2];
            ulonglong2 w0 = sW[p2 * 512 + 0 * 128 + u];
            ulonglong2 w1 = sW[p2 * 512 + 1 * 128 + u];
            ulonglong2 w2 = sW[p2 * 512 + 2 * 128 + u];
            ulonglong2 w3 = sW[p2 * 512 + 3 * 128 + u];
            A0a = ffma2(w0.x, hA.x, A0a); A0a = ffma2(w0.y, hA.y, A0a);
            A1a = ffma2(w1.x, hA.x, A1a); A1a = ffma2(w1.y, hA.y, A1a);
            A2a = ffma2(w2.x, hA.x, A2a); A2a = ffma2(w2.y, hA.y, A2a);
            A3a = ffma2(w3.x, hA.x, A3a); A3a = ffma2(w3.y, hA.y, A3a);
            A0b = ffma2(w0.x, hB.x, A0b); A0b = ffma2(w0.y, hB.y, A0b);
            A1b = ffma2(w1.x, hB.x, A1b); A1b = ffma2(w1.y, hB.y, A1b);
            A2b = ffma2(w2.x, hB.x, A2b); A2b = ffma2(w2.y, hB.y, A2b);
            A3b = ffma2(w3.x, hB.x, A3b); A3b = ffma2(w3.y, hB.y, A3b);
        }
        #pragma unroll
        for (int i = 0; i < NP2R; i++) {
            int p2 = NP2S + i;
            ulonglong2 hA = hb[m0 * 32 + p2];
            ulonglong2 hB = hb[m1 * 32 + p2];
            A0a = ffma2(wr[i][0].x, hA.x, A0a); A0a = ffma2(wr[i][0].y, hA.y, A0a);
            A1a = ffma2(wr[i][1].x, hA.x, A1a); A1a = ffma2(wr[i][1].y, hA.y, A1a);
            A2a = ffma2(wr[i][2].x, hA.x, A2a); A2a = ffma2(wr[i][2].y, hA.y, A2a);
            A3a = ffma2(wr[i][3].x, hA.x, A3a); A3a = ffma2(wr[i][3].y, hA.y, A3a);
            A0b = ffma2(wr[i][0].x, hB.x, A0b); A0b = ffma2(wr[i][0].y, hB.y, A0b);
            A1b = ffma2(wr[i][1].x, hB.x, A1b); A1b = ffma2(wr[i][1].y, hB.y, A1b);
            A2b = ffma2(wr[i][2].x, hB.x, A2b); A2b = ffma2(wr[i][2].y, hB.y, A2b);
            A3b = ffma2(wr[i][3].x, hB.x, A3b); A3b = ffma2(wr[i][3].y, hB.y, A3b);
        }

        // cell A (seq m0)
        {
            float xt = sx[m0 * TT + t];
            float pi = f2lo(A0a) + f2hi(A0a) + xt * wi[0] + bs[0];
            float pf = f2lo(A1a) + f2hi(A1a) + xt * wi[1] + bs[1];
            float pg = f2lo(A2a) + f2hi(A2a) + xt * wi[2] + bs[2];
            float po = f2lo(A3a) + f2hi(A3a) + xt * wi[3] + bs[3];
            cA = sigf(pf) * cA + sigf(pi) * tanh_(pg);
            float hv = sigf(po) * tanh_(cA);
            shf[nxt * 512 + m0 * 128 + u] = hv;
            if (t < lenA) hsA[(size_t)t * HH] = hv;
        }
        // cell B (seq m1)
        {
            float xt = sx[m1 * TT + t];
            float pi = f2lo(A0b) + f2hi(A0b) + xt * wi[0] + bs[0];
            float pf = f2lo(A1b) + f2hi(A1b) + xt * wi[1] + bs[1];
            float pg = f2lo(A2b) + f2hi(A2b) + xt * wi[2] + bs[2];
            float po = f2lo(A3b) + f2hi(A3b) + xt * wi[3] + bs[3];
            cB = sigf(pf) * cB + sigf(pi) * tanh_(pg);
            float hv = sigf(po) * tanh_(cB);
            shf[nxt * 512 + m1 * 128 + u] = hv;
            if (t < lenB) hsB[(size_t)t * HH] = hv;
        }
        __syncthreads();
    }

    // zero masked tails so the feats GEMM can ignore lengths
    for (int t = lenA; t < TT; t++) hsA[(size_t)t * HH] = 0.0f;
    for (int t = lenB; t < TT; t++) hsB[(size_t)t * HH] = 0.0f;
}

// ---------------- kernel 5: feats GEMM (split-K, tiled, f32x2) -------------------
// psum[kz][n][j] = sum_{t in chunk} sum_h hs[n][t][h] * W1[j][t*128+h]
__global__ void __launch_bounds__(256) k_feats(const float* __restrict__ W1) {
    __shared__ __align__(16) float sh_hs[TM][HH + 4];     // padded: conflict-free
    __shared__ __align__(16) float sh_w[NINTER][HH];

    int tile = blockIdx.x;        // 0..39
    int kz = blockIdx.y;          // 0..7
    int tid = threadIdx.x;
    int s0 = tid & 15;            // rows s0 and s0+16
    int j0 = (tid >> 4) * 4;      // 4 inter cols
    u64 a0[4] = {0, 0, 0, 0};
    u64 a1[4] = {0, 0, 0, 0};

    int t0 = kz * TCHUNK;
    for (int tt = 0; tt < TCHUNK; tt++) {
        int t = t0 + tt;
        __syncthreads();
        for (int i = tid; i < TM * 32; i += 256) {
            int s = i >> 5, kq = i & 31;
            ((float4*)&sh_hs[s][0])[kq] =
                ((const float4*)(g_hs + ((size_t)(tile * TM + s) * TT + t) * HH))[kq];
        }
        for (int i = tid; i < NINTER * 32; i += 256) {
            int j = i >> 5, kq = i & 31;
            ((float4*)&sh_w[j][0])[kq] =
                ((const float4*)(W1 + (size_t)j * (TT * HH) + (size_t)t * HH))[kq];
        }
        __syncthreads();
        #pragma unroll 4
        for (int kq = 0; kq < 32; kq++) {
            ulonglong2 hA = ((const ulonglong2*)&sh_hs[s0][0])[kq];
            ulonglong2 hB = ((const ulonglong2*)&sh_hs[s0 + 16][0])[kq];
            #pragma unroll
            for (int c = 0; c < 4; c++) {
                ulonglong2 w = ((const ulonglong2*)&sh_w[j0 + c][0])[kq];
                a0[c] = ffma2(hA.x, w.x, a0[c]); a0[c] = ffma2(hA.y, w.y, a0[c]);
                a1[c] = ffma2(hB.x, w.x, a1[c]); a1[c] = ffma2(hB.y, w.y, a1[c]);
            }
        }
    }
    int srow = tile * TM;
    size_t baseA = ((size_t)kz * NN + (srow + s0)) * NINTER + j0;
    size_t baseB = ((size_t)kz * NN + (srow + s0 + 16)) * NINTER + j0;
    #pragma unroll
    for (int c = 0; c < 4; c++) {
        g_psum[baseA + c] = f2lo(a0[c]) + f2hi(a0[c]);
        g_psum[baseB + c] = f2lo(a1[c]) + f2hi(a1[c]);
    }
}

// ---------------- kernel 6: reduce split-K + bias + final linear -----------------
__global__ void __launch_bounds__(256) k_final(
    const float* __restrict__ b1, const float* __restrict__ W2,
    const float* __restrict__ b2, float* __restrict__ out)
{
    __shared__ float sf[SS * NINTER];   // 1280 feats for this batch
    __shared__ float r0[256], r1[256];
    int b = blockIdx.x, tid = threadIdx.x;

    for (int i = tid; i < SS * NINTER; i += 256) {
        int s = i / NINTER, j = i % NINTER;
        size_t nq = (size_t)b * SS + s;
        float v = b1[j];
        #pragma unroll
        for (int kz = 0; kz < KSPLIT; kz++)
            v += g_psum[((size_t)kz * NN + nq) * NINTER + j];
        sf[i] = v;
    }
    __syncthreads();
    float p0 = 0.f, p1 = 0.f;
    for (int i = tid; i < SS * NINTER; i += 256) {
        float f = sf[i];
        p0 += f * W2[i];
        p1 += f * W2[SS * NINTER + i];
    }
    r0[tid] = p0; r1[tid] = p1;
    __syncthreads();
    for (int off = 128; off; off >>= 1) {
        if (tid < off) { r0[tid] += r0[tid + off]; r1[tid] += r1[tid + off]; }
        __syncthreads();
    }
    if (tid == 0) {
        out[b * 2 + 0] = r0[0] + b2[0];
        out[b * 2 + 1] = r1[0] + b2[1];
    }
}

// ---------------- launch ----------------------------------------------------------
extern "C" void kernel_launch(void* const* d_in, const int* in_sizes, int n_in,
                              void* d_out, int out_size)
{
    const float* x   = (const float*)d_in[0];
    // d_in[1] = metadata (unused by the reference computation)
    const float* Wih = (const float*)d_in[2];
    const float* Whh = (const float*)d_in[3];
    const float* bih = (const float*)d_in[4];
    const float* bhh = (const float*)d_in[5];
    const float* W1  = (const float*)d_in[6];
    const float* b1  = (const float*)d_in[7];
    const float* W2  = (const float*)d_in[8];
    const float* b2  = (const float*)d_in[9];
    float* out = (float*)d_out;

    cudaFuncSetAttribute(k_lstm, cudaFuncAttributeMaxDynamicSharedMemorySize, LSTM_SMEM);

    k_lens<<<NN, 32>>>(x);
    k_sort<<<1, 256>>>();
    k_wt<<<64, 256>>>(Whh);
    k_lstm<<<NGRP, 256, LSTM_SMEM>>>(x, Wih, bih, bhh);
    k_feats<<<dim3(40, KSPLIT), 256>>>(W1);
    k_final<<<BB, 256>>>(b1, W2, b2, out);
}

// round 15
// speedup vs baseline: 1.6911x; 1.6911x over previous
#include <cuda_runtime.h>
#include <cstdint>

#define TT     224
#define HH     128
#define BB     64
#define SS     20
#define NN     1280      // BB*SS
#define GM     4         // sequences per LSTM CTA
#define NGRP   320       // NN/GM
#define NINTER 64
#define KSPLIT 8
#define TM     32        // seq tile in feats GEMM
#define TCHUNK 28        // 224/KSPLIT timesteps per k-split

#define NP2S   24        // weight k-quads resident in smem
#define NP2R   8         // weight k-quads resident in registers

typedef unsigned long long u64;

// ---------------- scratch (static device globals; no runtime allocation) ---------
__device__ __align__(16) float g_hs[(size_t)NN * TT * HH];   // [n][t][h]
__device__ int   g_len[NN];
__device__ int   g_order[NN];
__device__ __align__(16) float g_Wk[512 * 128];              // [p2][r] float4: W[r][4p2..4p2+3]
__device__ __align__(16) float g_psum[(size_t)KSPLIT * NN * NINTER];

// ---------------- helpers ----------------
__device__ __forceinline__ u64 ffma2(u64 a, u64 b, u64 c) {
    u64 d;
    asm("fma.rn.f32x2 %0, %1, %2, %3;" : "=l"(d) : "l"(a), "l"(b), "l"(c));
    return d;
}
__device__ __forceinline__ float f2lo(u64 v) { return __uint_as_float((unsigned)(v & 0xffffffffull)); }
__device__ __forceinline__ float f2hi(u64 v) { return __uint_as_float((unsigned)(v >> 32)); }
__device__ __forceinline__ float tanhap(float v) {
    float r;
    asm("tanh.approx.f32 %0, %1;" : "=f"(r) : "f"(v));
    return r;
}
__device__ __forceinline__ float sigf(float v) {
    return fmaf(tanhap(0.5f * v), 0.5f, 0.5f);
}

// ---------------- kernel 1: ragged lengths ---------------------------------------
__global__ void k_lens(const float* __restrict__ x) {
    int n = blockIdx.x;
    const float* xs = x + (size_t)n * TT;
    int first = 1 << 30;
    for (int t = threadIdx.x; t < TT; t += 32)
        if (xs[t] == 0.0f) first = min(first, t);
    #pragma unroll
    for (int o = 16; o; o >>= 1)
        first = min(first, __shfl_xor_sync(0xffffffffu, first, o));
    if (threadIdx.x == 0)
        g_len[n] = (first == 0 || first >= TT) ? TT : (first + 1);
}

// ---------------- kernel 2: single-CTA counting sort by length -------------------
__global__ void __launch_bounds__(256) k_sort() {
    __shared__ int hist[256];
    __shared__ int off[256];
    int tid = threadIdx.x;
    hist[tid] = 0;
    __syncthreads();
    for (int n = tid; n < NN; n += 256) atomicAdd(&hist[g_len[n]], 1);
    __syncthreads();
    if (tid == 0) {
        int acc = 0;
        for (int i = 0; i < 256; i++) { off[i] = acc; acc += hist[i]; }
    }
    __syncthreads();
    for (int n = tid; n < NN; n += 256) {
        int pos = atomicAdd(&off[g_len[n]], 1);
        g_order[pos] = n;
    }
}

// ---------------- kernel 3: repack W_hh: g_Wk[p2*512 + r] = W[r][4p2..4p2+3] -----
__global__ void k_wt(const float* __restrict__ Whh) {
    int i = blockIdx.x * blockDim.x + threadIdx.x;   // 0..16383
    int r  = i & 511;
    int p2 = i >> 9;
    float4 v = ((const float4*)Whh)[r * 32 + p2];
    ((float4*)g_Wk)[p2 * 512 + r] = v;
}

// ---------------- kernel 4: LSTM (R13 structure, tanh.approx epilogue) -----------
// 256 threads; thread owns gate-rows r0 = tid (gate g0 = tid>>7) and r1 = tid+256
// (gate g0+2) for all 4 sequences. Gate exchange via spre smem; 2 barriers/step.
// Weight residency: 24 k-quads smem + 8 k-quads registers.
// dynamic smem:
//   [0, 196608)         sW   : ulonglong2[24*512]   weight k-quads p2=0..23
//   [196608, 200704)    shf  : float[2][4][128]     double-buffered h
//   [200704, 209152)    spre : float[16][132]       gate preacts (padded stride)
//   [209152, 212736)    sx   : float[4][224]
#define LSTM_SMEM 212736
#define SPRE_STR  132
__global__ void __launch_bounds__(256, 1) k_lstm(
    const float* __restrict__ x, const float* __restrict__ Wih,
    const float* __restrict__ bih, const float* __restrict__ bhh)
{
    extern __shared__ __align__(16) char dyn[];
    ulonglong2* sW = (ulonglong2*)dyn;
    float* shf  = (float*)(dyn + 196608);
    float* spre = (float*)(dyn + 200704);
    float* sx   = (float*)(dyn + 209152);
    __shared__ int sn[GM], sl[GM];

    int tid = threadIdx.x;
    int g0 = tid >> 7;          // gate of row r0 (0 or 1); r1 gate = g0+2
    int u  = tid & 127;
    int r0 = tid, r1 = tid + 256;

    int grp = (NGRP - 1) - blockIdx.x;   // longest groups scheduled first
    if (tid < GM) {
        int n = g_order[grp * GM + tid];
        sn[tid] = n;
        sl[tid] = g_len[n];
    }

    // stage smem weights (p2 = 0..23)
    const float4* Wk4 = (const float4*)g_Wk;
    float4* sW4 = (float4*)sW;
    for (int i = tid; i < NP2S * 512; i += 256) sW4[i] = Wk4[i];
    // zero both h buffers
    for (int i = tid; i < 1024; i += 256) shf[i] = 0.0f;

    // register weights (p2 = 24..31)
    ulonglong2 wr0[NP2R], wr1[NP2R];
    const ulonglong2* Wk2 = (const ulonglong2*)g_Wk;
    #pragma unroll
    for (int i = 0; i < NP2R; i++) {
        wr0[i] = Wk2[(size_t)(NP2S + i) * 512 + r0];
        wr1[i] = Wk2[(size_t)(NP2S + i) * 512 + r1];
    }

    float wi0 = Wih[r0], bs0 = bih[r0] + bhh[r0];
    float wi1 = Wih[r1], bs1 = bih[r1] + bhh[r1];

    __syncthreads();
    int maxlen = max(max(sl[0], sl[1]), max(sl[2], sl[3]));

    #pragma unroll
    for (int m = 0; m < GM; m++)
        for (int t = tid; t < TT; t += 256) sx[m * TT + t] = x[(size_t)sn[m] * TT + t];

    // this thread's 2 cells: (u, mA=g0) and (u, mB=g0+2)
    int mA = g0, mB = g0 + 2;
    int lenA = sl[mA], lenB = sl[mB];
    float* hsA = g_hs + (size_t)sn[mA] * TT * HH + u;
    float* hsB = g_hs + (size_t)sn[mB] * TT * HH + u;
    float cA = 0.0f, cB = 0.0f;
    __syncthreads();

    for (int t = 0; t < maxlen; t++) {
        int cur = t & 1, nxt = cur ^ 1;
        const ulonglong2* hb = (const ulonglong2*)(shf + cur * 512);

        u64 A00 = 0, A01 = 0, A02 = 0, A03 = 0;   // row r0, seqs 0..3
        u64 A10 = 0, A11 = 0, A12 = 0, A13 = 0;   // row r1, seqs 0..3

        #pragma unroll
        for (int p2 = 0; p2 < NP2S; p2++) {
            ulonglong2 w0 = sW[p2 * 512 + r0];
            ulonglong2 w1 = sW[p2 * 512 + r1];
            ulonglong2 h0 = hb[p2], h1 = hb[32 + p2], h2 = hb[64 + p2], h3 = hb[96 + p2];
            A00 = ffma2(w0.x, h0.x, A00); A00 = ffma2(w0.y, h0.y, A00);
            A01 = ffma2(w0.x, h1.x, A01); A01 = ffma2(w0.y, h1.y, A01);
            A02 = ffma2(w0.x, h2.x, A02); A02 = ffma2(w0.y, h2.y, A02);
            A03 = ffma2(w0.x, h3.x, A03); A03 = ffma2(w0.y, h3.y, A03);
            A10 = ffma2(w1.x, h0.x, A10); A10 = ffma2(w1.y, h0.y, A10);
            A11 = ffma2(w1.x, h1.x, A11); A11 = ffma2(w1.y, h1.y, A11);
            A12 = ffma2(w1.x, h2.x, A12); A12 = ffma2(w1.y, h2.y, A12);
            A13 = ffma2(w1.x, h3.x, A13); A13 = ffma2(w1.y, h3.y, A13);
        }
        #pragma unroll
        for (int i = 0; i < NP2R; i++) {
            int p2 = NP2S + i;
            ulonglong2 w0 = wr0[i];
            ulonglong2 w1 = wr1[i];
            ulonglong2 h0 = hb[p2], h1 = hb[32 + p2], h2 = hb[64 + p2], h3 = hb[96 + p2];
            A00 = ffma2(w0.x, h0.x, A00); A00 = ffma2(w0.y, h0.y, A00);
            A01 = ffma2(w0.x, h1.x, A01); A01 = ffma2(w0.y, h1.y, A01);
            A02 = ffma2(w0.x, h2.x, A02); A02 = ffma2(w0.y, h2.y, A02);
            A03 = ffma2(w0.x, h3.x, A03); A03 = ffma2(w0.y, h3.y, A03);
            A10 = ffma2(w1.x, h0.x, A10); A10 = ffma2(w1.y, h0.y, A10);
            A11 = ffma2(w1.x, h1.x, A11); A11 = ffma2(w1.y, h1.y, A11);
            A12 = ffma2(w1.x, h2.x, A12); A12 = ffma2(w1.y, h2.y, A12);
            A13 = ffma2(w1.x, h3.x, A13); A13 = ffma2(w1.y, h3.y, A13);
        }

        float xt0 = sx[t], xt1 = sx[TT + t], xt2 = sx[2 * TT + t], xt3 = sx[3 * TT + t];
        // pre-activations for this thread's two gate-rows, 4 seqs
        spre[((g0)     * 4 + 0) * SPRE_STR + u] = f2lo(A00) + f2hi(A00) + xt0 * wi0 + bs0;
        spre[((g0)     * 4 + 1) * SPRE_STR + u] = f2lo(A01) + f2hi(A01) + xt1 * wi0 + bs0;
        spre[((g0)     * 4 + 2) * SPRE_STR + u] = f2lo(A02) + f2hi(A02) + xt2 * wi0 + bs0;
        spre[((g0)     * 4 + 3) * SPRE_STR + u] = f2lo(A03) + f2hi(A03) + xt3 * wi0 + bs0;
        spre[((g0 + 2) * 4 + 0) * SPRE_STR + u] = f2lo(A10) + f2hi(A10) + xt0 * wi1 + bs1;
        spre[((g0 + 2) * 4 + 1) * SPRE_STR + u] = f2lo(A11) + f2hi(A11) + xt1 * wi1 + bs1;
        spre[((g0 + 2) * 4 + 2) * SPRE_STR + u] = f2lo(A12) + f2hi(A12) + xt2 * wi1 + bs1;
        spre[((g0 + 2) * 4 + 3) * SPRE_STR + u] = f2lo(A13) + f2hi(A13) + xt3 * wi1 + bs1;
        __syncthreads();

        // cell updates (2 cells per thread)
        {
            float pi = spre[(0 * 4 + mA) * SPRE_STR + u];
            float pf = spre[(1 * 4 + mA) * SPRE_STR + u];
            float pg = spre[(2 * 4 + mA) * SPRE_STR + u];
            float po = spre[(3 * 4 + mA) * SPRE_STR + u];
            cA = sigf(pf) * cA + sigf(pi) * tanhap(pg);
            float hv = sigf(po) * tanhap(cA);
            shf[nxt * 512 + mA * 128 + u] = hv;
            if (t < lenA) hsA[(size_t)t * HH] = hv;
        }
        {
            float pi = spre[(0 * 4 + mB) * SPRE_STR + u];
            float pf = spre[(1 * 4 + mB) * SPRE_STR + u];
            float pg = spre[(2 * 4 + mB) * SPRE_STR + u];
            float po = spre[(3 * 4 + mB) * SPRE_STR + u];
            cB = sigf(pf) * cB + sigf(pi) * tanhap(pg);
            float hv = sigf(po) * tanhap(cB);
            shf[nxt * 512 + mB * 128 + u] = hv;
            if (t < lenB) hsB[(size_t)t * HH] = hv;
        }
        __syncthreads();
    }

    // zero masked tails so the feats GEMM can ignore lengths
    for (int t = lenA; t < TT; t++) hsA[(size_t)t * HH] = 0.0f;
    for (int t = lenB; t < TT; t++) hsB[(size_t)t * HH] = 0.0f;
}

// ---------------- kernel 5: feats GEMM (split-K, tiled, f32x2) -------------------
// psum[kz][n][j] = sum_{t in chunk} sum_h hs[n][t][h] * W1[j][t*128+h]
__global__ void __launch_bounds__(256) k_feats(const float* __restrict__ W1) {
    __shared__ __align__(16) float sh_hs[TM][HH + 4];     // padded: conflict-free
    __shared__ __align__(16) float sh_w[NINTER][HH];

    int tile = blockIdx.x;        // 0..39
    int kz = blockIdx.y;          // 0..7
    int tid = threadIdx.x;
    int s0 = tid & 15;            // rows s0 and s0+16
    int j0 = (tid >> 4) * 4;      // 4 inter cols
    u64 a0[4] = {0, 0, 0, 0};
    u64 a1[4] = {0, 0, 0, 0};

    int t0 = kz * TCHUNK;
    for (int tt = 0; tt < TCHUNK; tt++) {
        int t = t0 + tt;
        __syncthreads();
        for (int i = tid; i < TM * 32; i += 256) {
            int s = i >> 5, kq = i & 31;
            ((float4*)&sh_hs[s][0])[kq] =
                ((const float4*)(g_hs + ((size_t)(tile * TM + s) * TT + t) * HH))[kq];
        }
        for (int i = tid; i < NINTER * 32; i += 256) {
            int j = i >> 5, kq = i & 31;
            ((float4*)&sh_w[j][0])[kq] =
                ((const float4*)(W1 + (size_t)j * (TT * HH) + (size_t)t * HH))[kq];
        }
        __syncthreads();
        #pragma unroll 4
        for (int kq = 0; kq < 32; kq++) {
            ulonglong2 hA = ((const ulonglong2*)&sh_hs[s0][0])[kq];
            ulonglong2 hB = ((const ulonglong2*)&sh_hs[s0 + 16][0])[kq];
            #pragma unroll
            for (int c = 0; c < 4; c++) {
                ulonglong2 w = ((const ulonglong2*)&sh_w[j0 + c][0])[kq];
                a0[c] = ffma2(hA.x, w.x, a0[c]); a0[c] = ffma2(hA.y, w.y, a0[c]);
                a1[c] = ffma2(hB.x, w.x, a1[c]); a1[c] = ffma2(hB.y, w.y, a1[c]);
            }
        }
    }
    int srow = tile * TM;
    size_t baseA = ((size_t)kz * NN + (srow + s0)) * NINTER + j0;
    size_t baseB = ((size_t)kz * NN + (srow + s0 + 16)) * NINTER + j0;
    #pragma unroll
    for (int c = 0; c < 4; c++) {
        g_psum[baseA + c] = f2lo(a0[c]) + f2hi(a0[c]);
        g_psum[baseB + c] = f2lo(a1[c]) + f2hi(a1[c]);
    }
}

// ---------------- kernel 6: reduce split-K + bias + final linear -----------------
__global__ void __launch_bounds__(256) k_final(
    const float* __restrict__ b1, const float* __restrict__ W2,
    const float* __restrict__ b2, float* __restrict__ out)
{
    __shared__ float sf[SS * NINTER];   // 1280 feats for this batch
    __shared__ float r0[256], r1[256];
    int b = blockIdx.x, tid = threadIdx.x;

    for (int i = tid; i < SS * NINTER; i += 256) {
        int s = i / NINTER, j = i % NINTER;
        size_t nq = (size_t)b * SS + s;
        float v = b1[j];
        #pragma unroll
        for (int kz = 0; kz < KSPLIT; kz++)
            v += g_psum[((size_t)kz * NN + nq) * NINTER + j];
        sf[i] = v;
    }
    __syncthreads();
    float p0 = 0.f, p1 = 0.f;
    for (int i = tid; i < SS * NINTER; i += 256) {
        float f = sf[i];
        p0 += f * W2[i];
        p1 += f * W2[SS * NINTER + i];
    }
    r0[tid] = p0; r1[tid] = p1;
    __syncthreads();
    for (int off = 128; off; off >>= 1) {
        if (tid < off) { r0[tid] += r0[tid + off]; r1[tid] += r1[tid + off]; }
        __syncthreads();
    }
    if (tid == 0) {
        out[b * 2 + 0] = r0[0] + b2[0];
        out[b * 2 + 1] = r1[0] + b2[1];
    }
}

// ---------------- launch ----------------------------------------------------------
extern "C" void kernel_launch(void* const* d_in, const int* in_sizes, int n_in,
                              void* d_out, int out_size)
{
    const float* x   = (const float*)d_in[0];
    // d_in[1] = metadata (unused by the reference computation)
    const float* Wih = (const float*)d_in[2];
    const float* Whh = (const float*)d_in[3];
    const float* bih = (const float*)d_in[4];
    const float* bhh = (const float*)d_in[5];
    const float* W1  = (const float*)d_in[6];
    const float* b1  = (const float*)d_in[7];
    const float* W2  = (const float*)d_in[8];
    const float* b2  = (const float*)d_in[9];
    float* out = (float*)d_out;

    cudaFuncSetAttribute(k_lstm, cudaFuncAttributeMaxDynamicSharedMemorySize, LSTM_SMEM);

    k_lens<<<NN, 32>>>(x);
    k_sort<<<1, 256>>>();
    k_wt<<<64, 256>>>(Whh);
    k_lstm<<<NGRP, 256, LSTM_SMEM>>>(x, Wih, bih, bhh);
    k_feats<<<dim3(40, KSPLIT), 256>>>(W1);
    k_final<<<BB, 256>>>(b1, W2, b2, out);
}

// round 16
// speedup vs baseline: 1.8814x; 1.1126x over previous
#include <cuda_runtime.h>
#include <cstdint>

#define TT     224
#define HH     128
#define BB     64
#define SS     20
#define NN     1280      // BB*SS
#define GM     4         // sequences per LSTM CTA
#define NGRP   320       // NN/GM
#define NINTER 64
#define KSPLIT 14
#define TM     64        // seq tile in feats GEMM
#define TCHUNK 16        // 224/KSPLIT timesteps per k-split

#define NP2S   22        // weight k-quads resident in smem
#define NP2R   10        // weight k-quads resident in registers

typedef unsigned long long u64;

// ---------------- scratch (static device globals; no runtime allocation) ---------
__device__ __align__(16) float g_hs[(size_t)NN * TT * HH];   // [n][t][h]
__device__ int   g_len[NN];
__device__ int   g_order[NN];
__device__ __align__(16) float g_Wk[512 * 128];              // [p2][r] float4: W[r][4p2..4p2+3]
__device__ __align__(16) float g_psum[(size_t)KSPLIT * NN * NINTER];

// ---------------- helpers ----------------
__device__ __forceinline__ u64 ffma2(u64 a, u64 b, u64 c) {
    u64 d;
    asm("fma.rn.f32x2 %0, %1, %2, %3;" : "=l"(d) : "l"(a), "l"(b), "l"(c));
    return d;
}
__device__ __forceinline__ float f2lo(u64 v) { return __uint_as_float((unsigned)(v & 0xffffffffull)); }
__device__ __forceinline__ float f2hi(u64 v) { return __uint_as_float((unsigned)(v >> 32)); }
__device__ __forceinline__ float tanhap(float v) {
    float r;
    asm("tanh.approx.f32 %0, %1;" : "=f"(r) : "f"(v));
    return r;
}
__device__ __forceinline__ float sigf(float v) {
    return fmaf(tanhap(0.5f * v), 0.5f, 0.5f);
}

// ---------------- kernel 1: ragged lengths ---------------------------------------
__global__ void k_lens(const float* __restrict__ x) {
    int n = blockIdx.x;
    const float* xs = x + (size_t)n * TT;
    int first = 1 << 30;
    for (int t = threadIdx.x; t < TT; t += 32)
        if (xs[t] == 0.0f) first = min(first, t);
    #pragma unroll
    for (int o = 16; o; o >>= 1)
        first = min(first, __shfl_xor_sync(0xffffffffu, first, o));
    if (threadIdx.x == 0)
        g_len[n] = (first == 0 || first >= TT) ? TT : (first + 1);
}

// ---------------- kernel 2: single-CTA counting sort by length -------------------
__global__ void __launch_bounds__(256) k_sort() {
    __shared__ int hist[256];
    __shared__ int off[256];
    int tid = threadIdx.x;
    hist[tid] = 0;
    __syncthreads();
    for (int n = tid; n < NN; n += 256) atomicAdd(&hist[g_len[n]], 1);
    __syncthreads();
    if (tid == 0) {
        int acc = 0;
        for (int i = 0; i < 256; i++) { off[i] = acc; acc += hist[i]; }
    }
    __syncthreads();
    for (int n = tid; n < NN; n += 256) {
        int pos = atomicAdd(&off[g_len[n]], 1);
        g_order[pos] = n;
    }
}

// ---------------- kernel 3: repack W_hh: g_Wk[p2*512 + r] = W[r][4p2..4p2+3] -----
__global__ void k_wt(const float* __restrict__ Whh) {
    int i = blockIdx.x * blockDim.x + threadIdx.x;   // 0..16383
    int r  = i & 511;
    int p2 = i >> 9;
    float4 v = ((const float4*)Whh)[r * 32 + p2];
    ((float4*)g_Wk)[p2 * 512 + r] = v;
}

// ---------------- kernel 4: LSTM (R15 structure, 22/10 weight split) -------------
// 256 threads; thread owns gate-rows r0 = tid (gate g0 = tid>>7) and r1 = tid+256
// (gate g0+2) for all 4 sequences. Gate exchange via spre smem; 2 barriers/step.
// dynamic smem:
//   [0, 180224)         sW   : ulonglong2[22*512]   weight k-quads p2=0..21
//   [180224, 184320)    shf  : float[2][4][128]     double-buffered h
//   [184320, 192768)    spre : float[16][132]       gate preacts (padded stride)
//   [192768, 196352)    sx   : float[4][224]
#define LSTM_SMEM 196352
#define SPRE_STR  132
__global__ void __launch_bounds__(256, 1) k_lstm(
    const float* __restrict__ x, const float* __restrict__ Wih,
    const float* __restrict__ bih, const float* __restrict__ bhh)
{
    extern __shared__ __align__(16) char dyn[];
    ulonglong2* sW = (ulonglong2*)dyn;
    float* shf  = (float*)(dyn + 180224);
    float* spre = (float*)(dyn + 184320);
    float* sx   = (float*)(dyn + 192768);
    __shared__ int sn[GM], sl[GM];

    int tid = threadIdx.x;
    int g0 = tid >> 7;          // gate of row r0 (0 or 1); r1 gate = g0+2
    int u  = tid & 127;
    int r0 = tid, r1 = tid + 256;

    int grp = (NGRP - 1) - blockIdx.x;   // longest groups scheduled first
    if (tid < GM) {
        int n = g_order[grp * GM + tid];
        sn[tid] = n;
        sl[tid] = g_len[n];
    }

    // stage smem weights (p2 = 0..21)
    const float4* Wk4 = (const float4*)g_Wk;
    float4* sW4 = (float4*)sW;
    for (int i = tid; i < NP2S * 512; i += 256) sW4[i] = Wk4[i];
    // zero both h buffers
    for (int i = tid; i < 1024; i += 256) shf[i] = 0.0f;

    // register weights (p2 = 22..31)
    ulonglong2 wr0[NP2R], wr1[NP2R];
    const ulonglong2* Wk2 = (const ulonglong2*)g_Wk;
    #pragma unroll
    for (int i = 0; i < NP2R; i++) {
        wr0[i] = Wk2[(size_t)(NP2S + i) * 512 + r0];
        wr1[i] = Wk2[(size_t)(NP2S + i) * 512 + r1];
    }

    float wi0 = Wih[r0], bs0 = bih[r0] + bhh[r0];
    float wi1 = Wih[r1], bs1 = bih[r1] + bhh[r1];

    __syncthreads();
    int maxlen = max(max(sl[0], sl[1]), max(sl[2], sl[3]));

    #pragma unroll
    for (int m = 0; m < GM; m++)
        for (int t = tid; t < TT; t += 256) sx[m * TT + t] = x[(size_t)sn[m] * TT + t];

    // this thread's 2 cells: (u, mA=g0) and (u, mB=g0+2)
    int mA = g0, mB = g0 + 2;
    int lenA = sl[mA], lenB = sl[mB];
    float* hsA = g_hs + (size_t)sn[mA] * TT * HH + u;
    float* hsB = g_hs + (size_t)sn[mB] * TT * HH + u;
    float cA = 0.0f, cB = 0.0f;
    __syncthreads();

    for (int t = 0; t < maxlen; t++) {
        int cur = t & 1, nxt = cur ^ 1;
        const ulonglong2* hb = (const ulonglong2*)(shf + cur * 512);

        u64 A00 = 0, A01 = 0, A02 = 0, A03 = 0;   // row r0, seqs 0..3
        u64 A10 = 0, A11 = 0, A12 = 0, A13 = 0;   // row r1, seqs 0..3

        #pragma unroll
        for (int p2 = 0; p2 < NP2S; p2++) {
            ulonglong2 w0 = sW[p2 * 512 + r0];
            ulonglong2 w1 = sW[p2 * 512 + r1];
            ulonglong2 h0 = hb[p2], h1 = hb[32 + p2], h2 = hb[64 + p2], h3 = hb[96 + p2];
            A00 = ffma2(w0.x, h0.x, A00); A00 = ffma2(w0.y, h0.y, A00);
            A01 = ffma2(w0.x, h1.x, A01); A01 = ffma2(w0.y, h1.y, A01);
            A02 = ffma2(w0.x, h2.x, A02); A02 = ffma2(w0.y, h2.y, A02);
            A03 = ffma2(w0.x, h3.x, A03); A03 = ffma2(w0.y, h3.y, A03);
            A10 = ffma2(w1.x, h0.x, A10); A10 = ffma2(w1.y, h0.y, A10);
            A11 = ffma2(w1.x, h1.x, A11); A11 = ffma2(w1.y, h1.y, A11);
            A12 = ffma2(w1.x, h2.x, A12); A12 = ffma2(w1.y, h2.y, A12);
            A13 = ffma2(w1.x, h3.x, A13); A13 = ffma2(w1.y, h3.y, A13);
        }
        #pragma unroll
        for (int i = 0; i < NP2R; i++) {
            int p2 = NP2S + i;
            ulonglong2 w0 = wr0[i];
            ulonglong2 w1 = wr1[i];
            ulonglong2 h0 = hb[p2], h1 = hb[32 + p2], h2 = hb[64 + p2], h3 = hb[96 + p2];
            A00 = ffma2(w0.x, h0.x, A00); A00 = ffma2(w0.y, h0.y, A00);
            A01 = ffma2(w0.x, h1.x, A01); A01 = ffma2(w0.y, h1.y, A01);
            A02 = ffma2(w0.x, h2.x, A02); A02 = ffma2(w0.y, h2.y, A02);
            A03 = ffma2(w0.x, h3.x, A03); A03 = ffma2(w0.y, h3.y, A03);
            A10 = ffma2(w1.x, h0.x, A10); A10 = ffma2(w1.y, h0.y, A10);
            A11 = ffma2(w1.x, h1.x, A11); A11 = ffma2(w1.y, h1.y, A11);
            A12 = ffma2(w1.x, h2.x, A12); A12 = ffma2(w1.y, h2.y, A12);
            A13 = ffma2(w1.x, h3.x, A13); A13 = ffma2(w1.y, h3.y, A13);
        }

        float xt0 = sx[t], xt1 = sx[TT + t], xt2 = sx[2 * TT + t], xt3 = sx[3 * TT + t];
        // pre-activations for this thread's two gate-rows, 4 seqs
        spre[((g0)     * 4 + 0) * SPRE_STR + u] = f2lo(A00) + f2hi(A00) + xt0 * wi0 + bs0;
        spre[((g0)     * 4 + 1) * SPRE_STR + u] = f2lo(A01) + f2hi(A01) + xt1 * wi0 + bs0;
        spre[((g0)     * 4 + 2) * SPRE_STR + u] = f2lo(A02) + f2hi(A02) + xt2 * wi0 + bs0;
        spre[((g0)     * 4 + 3) * SPRE_STR + u] = f2lo(A03) + f2hi(A03) + xt3 * wi0 + bs0;
        spre[((g0 + 2) * 4 + 0) * SPRE_STR + u] = f2lo(A10) + f2hi(A10) + xt0 * wi1 + bs1;
        spre[((g0 + 2) * 4 + 1) * SPRE_STR + u] = f2lo(A11) + f2hi(A11) + xt1 * wi1 + bs1;
        spre[((g0 + 2) * 4 + 2) * SPRE_STR + u] = f2lo(A12) + f2hi(A12) + xt2 * wi1 + bs1;
        spre[((g0 + 2) * 4 + 3) * SPRE_STR + u] = f2lo(A13) + f2hi(A13) + xt3 * wi1 + bs1;
        __syncthreads();

        // cell updates (2 cells per thread)
        {
            float pi = spre[(0 * 4 + mA) * SPRE_STR + u];
            float pf = spre[(1 * 4 + mA) * SPRE_STR + u];
            float pg = spre[(2 * 4 + mA) * SPRE_STR + u];
            float po = spre[(3 * 4 + mA) * SPRE_STR + u];
            cA = sigf(pf) * cA + sigf(pi) * tanhap(pg);
            float hv = sigf(po) * tanhap(cA);
            shf[nxt * 512 + mA * 128 + u] = hv;
            if (t < lenA) hsA[(size_t)t * HH] = hv;
        }
        {
            float pi = spre[(0 * 4 + mB) * SPRE_STR + u];
            float pf = spre[(1 * 4 + mB) * SPRE_STR + u];
            float pg = spre[(2 * 4 + mB) * SPRE_STR + u];
            float po = spre[(3 * 4 + mB) * SPRE_STR + u];
            cB = sigf(pf) * cB + sigf(pi) * tanhap(pg);
            float hv = sigf(po) * tanhap(cB);
            shf[nxt * 512 + mB * 128 + u] = hv;
            if (t < lenB) hsB[(size_t)t * HH] = hv;
        }
        __syncthreads();
    }

    // zero masked tails so the feats GEMM can ignore lengths
    for (int t = lenA; t < TT; t++) hsA[(size_t)t * HH] = 0.0f;
    for (int t = lenB; t < TT; t++) hsB[(size_t)t * HH] = 0.0f;
}

// ---------------- kernel 5: feats GEMM (split-K, 64x64 tile, 4x4/thread) ---------
// psum[kz][n][j] = sum_{t in chunk} sum_h hs[n][t][h] * W1[j][t*128+h]
__global__ void __launch_bounds__(256) k_feats(const float* __restrict__ W1) {
    __shared__ __align__(16) float sh_hs[TM][HH + 4];     // padded rows
    __shared__ __align__(16) float sh_w[NINTER][HH + 4];

    int tile = blockIdx.x;        // 0..19
    int kz = blockIdx.y;          // 0..13
    int tid = threadIdx.x;
    int rr = tid & 15;            // rows rr, rr+16, rr+32, rr+48
    int j0 = (tid >> 4) * 4;      // 4 inter cols
    u64 a[4][4];
    #pragma unroll
    for (int r = 0; r < 4; r++)
        #pragma unroll
        for (int c = 0; c < 4; c++) a[r][c] = 0;

    int t0 = kz * TCHUNK;
    for (int tt = 0; tt < TCHUNK; tt++) {
        int t = t0 + tt;
        __syncthreads();
        for (int i = tid; i < TM * 32; i += 256) {
            int s = i >> 5, kq = i & 31;
            ((float4*)&sh_hs[s][0])[kq] =
                ((const float4*)(g_hs + ((size_t)(tile * TM + s) * TT + t) * HH))[kq];
        }
        for (int i = tid; i < NINTER * 32; i += 256) {
            int j = i >> 5, kq = i & 31;
            ((float4*)&sh_w[j][0])[kq] =
                ((const float4*)(W1 + (size_t)j * (TT * HH) + (size_t)t * HH))[kq];
        }
        __syncthreads();
        #pragma unroll 4
        for (int kq = 0; kq < 32; kq++) {
            ulonglong2 h[4], w[4];
            #pragma unroll
            for (int r = 0; r < 4; r++)
                h[r] = ((const ulonglong2*)&sh_hs[rr + 16 * r][0])[kq];
            #pragma unroll
            for (int c = 0; c < 4; c++)
                w[c] = ((const ulonglong2*)&sh_w[j0 + c][0])[kq];
            #pragma unroll
            for (int r = 0; r < 4; r++)
                #pragma unroll
                for (int c = 0; c < 4; c++) {
                    a[r][c] = ffma2(h[r].x, w[c].x, a[r][c]);
                    a[r][c] = ffma2(h[r].y, w[c].y, a[r][c]);
                }
        }
    }
    #pragma unroll
    for (int r = 0; r < 4; r++) {
        size_t base = ((size_t)kz * NN + (tile * TM + rr + 16 * r)) * NINTER + j0;
        #pragma unroll
        for (int c = 0; c < 4; c++)
            g_psum[base + c] = f2lo(a[r][c]) + f2hi(a[r][c]);
    }
}

// ---------------- kernel 6: reduce split-K + bias + final linear -----------------
__global__ void __launch_bounds__(256) k_final(
    const float* __restrict__ b1, const float* __restrict__ W2,
    const float* __restrict__ b2, float* __restrict__ out)
{
    __shared__ float sf[SS * NINTER];   // 1280 feats for this batch
    __shared__ float r0[256], r1[256];
    int b = blockIdx.x, tid = threadIdx.x;

    for (int i = tid; i < SS * NINTER; i += 256) {
        int s = i / NINTER, j = i % NINTER;
        size_t nq = (size_t)b * SS + s;
        float v = b1[j];
        #pragma unroll
        for (int kz = 0; kz < KSPLIT; kz++)
            v += g_psum[((size_t)kz * NN + nq) * NINTER + j];
        sf[i] = v;
    }
    __syncthreads();
    float p0 = 0.f, p1 = 0.f;
    for (int i = tid; i < SS * NINTER; i += 256) {
        float f = sf[i];
        p0 += f * W2[i];
        p1 += f * W2[SS * NINTER + i];
    }
    r0[tid] = p0; r1[tid] = p1;
    __syncthreads();
    for (int off = 128; off; off >>= 1) {
        if (tid < off) { r0[tid] += r0[tid + off]; r1[tid] += r1[tid + off]; }
        __syncthreads();
    }
    if (tid == 0) {
        out[b * 2 + 0] = r0[0] + b2[0];
        out[b * 2 + 1] = r1[0] + b2[1];
    }
}

// ---------------- launch ----------------------------------------------------------
extern "C" void kernel_launch(void* const* d_in, const int* in_sizes, int n_in,
                              void* d_out, int out_size)
{
    const float* x   = (const float*)d_in[0];
    // d_in[1] = metadata (unused by the reference computation)
    const float* Wih = (const float*)d_in[2];
    const float* Whh = (const float*)d_in[3];
    const float* bih = (const float*)d_in[4];
    const float* bhh = (const float*)d_in[5];
    const float* W1  = (const float*)d_in[6];
    const float* b1  = (const float*)d_in[7];
    const float* W2  = (const float*)d_in[8];
    const float* b2  = (const float*)d_in[9];
    float* out = (float*)d_out;

    cudaFuncSetAttribute(k_lstm, cudaFuncAttributeMaxDynamicSharedMemorySize, LSTM_SMEM);

    k_lens<<<NN, 32>>>(x);
    k_sort<<<1, 256>>>();
    k_wt<<<64, 256>>>(Whh);
    k_lstm<<<NGRP, 256, LSTM_SMEM>>>(x, Wih, bih, bhh);
    k_feats<<<dim3(20, KSPLIT), 256>>>(W1);
    k_final<<<BB, 256>>>(b1, W2, b2, out);
}

// round 17
// speedup vs baseline: 1.9211x; 1.0211x over previous
#include <cuda_runtime.h>
#include <cstdint>

#define TT     224
#define HH     128
#define BB     64
#define SS     20
#define NN     1280      // BB*SS
#define GM     4         // sequences per LSTM CTA
#define NGRP   320       // NN/GM
#define NINTER 64
#define KSPLIT 14
#define TM     64        // seq tile in feats GEMM
#define TCHUNK 16        // 224/KSPLIT timesteps per k-split

#define NP2S   20        // weight k-quads resident in smem
#define NP2R   12        // weight k-quads resident in registers

typedef unsigned long long u64;

// ---------------- scratch (static device globals; no runtime allocation) ---------
__device__ __align__(16) float g_hs[(size_t)NN * TT * HH];   // [n][t][h]
__device__ int   g_len[NN];
__device__ int   g_order[NN];
__device__ __align__(16) float g_Wk[512 * 128];              // [p2][r] float4: W[r][4p2..4p2+3]
__device__ __align__(16) float g_psum[(size_t)KSPLIT * NN * NINTER];

// ---------------- helpers ----------------
__device__ __forceinline__ u64 ffma2(u64 a, u64 b, u64 c) {
    u64 d;
    asm("fma.rn.f32x2 %0, %1, %2, %3;" : "=l"(d) : "l"(a), "l"(b), "l"(c));
    return d;
}
__device__ __forceinline__ float f2lo(u64 v) { return __uint_as_float((unsigned)(v & 0xffffffffull)); }
__device__ __forceinline__ float f2hi(u64 v) { return __uint_as_float((unsigned)(v >> 32)); }
__device__ __forceinline__ float tanhap(float v) {
    float r;
    asm("tanh.approx.f32 %0, %1;" : "=f"(r) : "f"(v));
    return r;
}
__device__ __forceinline__ float sigf(float v) {
    return fmaf(tanhap(0.5f * v), 0.5f, 0.5f);
}

// ---------------- kernel 1: ragged lengths ---------------------------------------
__global__ void k_lens(const float* __restrict__ x) {
    int n = blockIdx.x;
    const float* xs = x + (size_t)n * TT;
    int first = 1 << 30;
    for (int t = threadIdx.x; t < TT; t += 32)
        if (xs[t] == 0.0f) first = min(first, t);
    #pragma unroll
    for (int o = 16; o; o >>= 1)
        first = min(first, __shfl_xor_sync(0xffffffffu, first, o));
    if (threadIdx.x == 0)
        g_len[n] = (first == 0 || first >= TT) ? TT : (first + 1);
}

// ---------------- kernel 2: single-CTA counting sort by length -------------------
__global__ void __launch_bounds__(256) k_sort() {
    __shared__ int hist[256];
    __shared__ int off[256];
    int tid = threadIdx.x;
    hist[tid] = 0;
    __syncthreads();
    for (int n = tid; n < NN; n += 256) atomicAdd(&hist[g_len[n]], 1);
    __syncthreads();
    if (tid == 0) {
        int acc = 0;
        for (int i = 0; i < 256; i++) { off[i] = acc; acc += hist[i]; }
    }
    __syncthreads();
    for (int n = tid; n < NN; n += 256) {
        int pos = atomicAdd(&off[g_len[n]], 1);
        g_order[pos] = n;
    }
}

// ---------------- kernel 3: repack W_hh: g_Wk[p2*512 + r] = W[r][4p2..4p2+3] -----
__global__ void k_wt(const float* __restrict__ Whh) {
    int i = blockIdx.x * blockDim.x + threadIdx.x;   // 0..16383
    int r  = i & 511;
    int p2 = i >> 9;
    float4 v = ((const float4*)Whh)[r * 32 + p2];
    ((float4*)g_Wk)[p2 * 512 + r] = v;
}

// ---------------- kernel 4: LSTM (R16 structure, 20/12 weight split) -------------
// 256 threads; thread owns gate-rows r0 = tid (gate g0 = tid>>7) and r1 = tid+256
// (gate g0+2) for all 4 sequences. Gate exchange via spre smem; 2 barriers/step.
// dynamic smem:
//   [0, 163840)         sW   : ulonglong2[20*512]   weight k-quads p2=0..19
//   [163840, 167936)    shf  : float[2][4][128]     double-buffered h
//   [167936, 176384)    spre : float[16][132]       gate preacts (padded stride)
//   [176384, 179968)    sx   : float[4][224]
#define LSTM_SMEM 179968
#define SPRE_STR  132
__global__ void __launch_bounds__(256, 1) k_lstm(
    const float* __restrict__ x, const float* __restrict__ Wih,
    const float* __restrict__ bih, const float* __restrict__ bhh)
{
    extern __shared__ __align__(16) char dyn[];
    ulonglong2* sW = (ulonglong2*)dyn;
    float* shf  = (float*)(dyn + 163840);
    float* spre = (float*)(dyn + 167936);
    float* sx   = (float*)(dyn + 176384);
    __shared__ int sn[GM], sl[GM];

    int tid = threadIdx.x;
    int g0 = tid >> 7;          // gate of row r0 (0 or 1); r1 gate = g0+2
    int u  = tid & 127;
    int r0 = tid, r1 = tid + 256;

    int grp = (NGRP - 1) - blockIdx.x;   // longest groups scheduled first
    if (tid < GM) {
        int n = g_order[grp * GM + tid];
        sn[tid] = n;
        sl[tid] = g_len[n];
    }

    // stage smem weights (p2 = 0..19)
    const float4* Wk4 = (const float4*)g_Wk;
    float4* sW4 = (float4*)sW;
    for (int i = tid; i < NP2S * 512; i += 256) sW4[i] = Wk4[i];
    // zero both h buffers
    for (int i = tid; i < 1024; i += 256) shf[i] = 0.0f;

    // register weights (p2 = 20..31)
    ulonglong2 wr0[NP2R], wr1[NP2R];
    const ulonglong2* Wk2 = (const ulonglong2*)g_Wk;
    #pragma unroll
    for (int i = 0; i < NP2R; i++) {
        wr0[i] = Wk2[(size_t)(NP2S + i) * 512 + r0];
        wr1[i] = Wk2[(size_t)(NP2S + i) * 512 + r1];
    }

    float wi0 = Wih[r0], bs0 = bih[r0] + bhh[r0];
    float wi1 = Wih[r1], bs1 = bih[r1] + bhh[r1];

    __syncthreads();
    int maxlen = max(max(sl[0], sl[1]), max(sl[2], sl[3]));

    #pragma unroll
    for (int m = 0; m < GM; m++)
        for (int t = tid; t < TT; t += 256) sx[m * TT + t] = x[(size_t)sn[m] * TT + t];

    // this thread's 2 cells: (u, mA=g0) and (u, mB=g0+2)
    int mA = g0, mB = g0 + 2;
    int lenA = sl[mA], lenB = sl[mB];
    float* hsA = g_hs + (size_t)sn[mA] * TT * HH + u;
    float* hsB = g_hs + (size_t)sn[mB] * TT * HH + u;
    float cA = 0.0f, cB = 0.0f;
    __syncthreads();

    for (int t = 0; t < maxlen; t++) {
        int cur = t & 1, nxt = cur ^ 1;
        const ulonglong2* hb = (const ulonglong2*)(shf + cur * 512);

        u64 A00 = 0, A01 = 0, A02 = 0, A03 = 0;   // row r0, seqs 0..3
        u64 A10 = 0, A11 = 0, A12 = 0, A13 = 0;   // row r1, seqs 0..3

        #pragma unroll
        for (int p2 = 0; p2 < NP2S; p2++) {
            ulonglong2 w0 = sW[p2 * 512 + r0];
            ulonglong2 w1 = sW[p2 * 512 + r1];
            ulonglong2 h0 = hb[p2], h1 = hb[32 + p2], h2 = hb[64 + p2], h3 = hb[96 + p2];
            A00 = ffma2(w0.x, h0.x, A00); A00 = ffma2(w0.y, h0.y, A00);
            A01 = ffma2(w0.x, h1.x, A01); A01 = ffma2(w0.y, h1.y, A01);
            A02 = ffma2(w0.x, h2.x, A02); A02 = ffma2(w0.y, h2.y, A02);
            A03 = ffma2(w0.x, h3.x, A03); A03 = ffma2(w0.y, h3.y, A03);
            A10 = ffma2(w1.x, h0.x, A10); A10 = ffma2(w1.y, h0.y, A10);
            A11 = ffma2(w1.x, h1.x, A11); A11 = ffma2(w1.y, h1.y, A11);
            A12 = ffma2(w1.x, h2.x, A12); A12 = ffma2(w1.y, h2.y, A12);
            A13 = ffma2(w1.x, h3.x, A13); A13 = ffma2(w1.y, h3.y, A13);
        }
        #pragma unroll
        for (int i = 0; i < NP2R; i++) {
            int p2 = NP2S + i;
            ulonglong2 w0 = wr0[i];
            ulonglong2 w1 = wr1[i];
            ulonglong2 h0 = hb[p2], h1 = hb[32 + p2], h2 = hb[64 + p2], h3 = hb[96 + p2];
            A00 = ffma2(w0.x, h0.x, A00); A00 = ffma2(w0.y, h0.y, A00);
            A01 = ffma2(w0.x, h1.x, A01); A01 = ffma2(w0.y, h1.y, A01);
            A02 = ffma2(w0.x, h2.x, A02); A02 = ffma2(w0.y, h2.y, A02);
            A03 = ffma2(w0.x, h3.x, A03); A03 = ffma2(w0.y, h3.y, A03);
            A10 = ffma2(w1.x, h0.x, A10); A10 = ffma2(w1.y, h0.y, A10);
            A11 = ffma2(w1.x, h1.x, A11); A11 = ffma2(w1.y, h1.y, A11);
            A12 = ffma2(w1.x, h2.x, A12); A12 = ffma2(w1.y, h2.y, A12);
            A13 = ffma2(w1.x, h3.x, A13); A13 = ffma2(w1.y, h3.y, A13);
        }

        float xt0 = sx[t], xt1 = sx[TT + t], xt2 = sx[2 * TT + t], xt3 = sx[3 * TT + t];
        // pre-activations for this thread's two gate-rows, 4 seqs
        spre[((g0)     * 4 + 0) * SPRE_STR + u] = f2lo(A00) + f2hi(A00) + xt0 * wi0 + bs0;
        spre[((g0)     * 4 + 1) * SPRE_STR + u] = f2lo(A01) + f2hi(A01) + xt1 * wi0 + bs0;
        spre[((g0)     * 4 + 2) * SPRE_STR + u] = f2lo(A02) + f2hi(A02) + xt2 * wi0 + bs0;
        spre[((g0)     * 4 + 3) * SPRE_STR + u] = f2lo(A03) + f2hi(A03) + xt3 * wi0 + bs0;
        spre[((g0 + 2) * 4 + 0) * SPRE_STR + u] = f2lo(A10) + f2hi(A10) + xt0 * wi1 + bs1;
        spre[((g0 + 2) * 4 + 1) * SPRE_STR + u] = f2lo(A11) + f2hi(A11) + xt1 * wi1 + bs1;
        spre[((g0 + 2) * 4 + 2) * SPRE_STR + u] = f2lo(A12) + f2hi(A12) + xt2 * wi1 + bs1;
        spre[((g0 + 2) * 4 + 3) * SPRE_STR + u] = f2lo(A13) + f2hi(A13) + xt3 * wi1 + bs1;
        __syncthreads();

        // cell updates (2 cells per thread)
        {
            float pi = spre[(0 * 4 + mA) * SPRE_STR + u];
            float pf = spre[(1 * 4 + mA) * SPRE_STR + u];
            float pg = spre[(2 * 4 + mA) * SPRE_STR + u];
            float po = spre[(3 * 4 + mA) * SPRE_STR + u];
            cA = sigf(pf) * cA + sigf(pi) * tanhap(pg);
            float hv = sigf(po) * tanhap(cA);
            shf[nxt * 512 + mA * 128 + u] = hv;
            if (t < lenA) hsA[(size_t)t * HH] = hv;
        }
        {
            float pi = spre[(0 * 4 + mB) * SPRE_STR + u];
            float pf = spre[(1 * 4 + mB) * SPRE_STR + u];
            float pg = spre[(2 * 4 + mB) * SPRE_STR + u];
            float po = spre[(3 * 4 + mB) * SPRE_STR + u];
            cB = sigf(pf) * cB + sigf(pi) * tanhap(pg);
            float hv = sigf(po) * tanhap(cB);
            shf[nxt * 512 + mB * 128 + u] = hv;
            if (t < lenB) hsB[(size_t)t * HH] = hv;
        }
        __syncthreads();
    }

    // zero masked tails so the feats GEMM can ignore lengths
    for (int t = lenA; t < TT; t++) hsA[(size_t)t * HH] = 0.0f;
    for (int t = lenB; t < TT; t++) hsB[(size_t)t * HH] = 0.0f;
}

// ---------------- kernel 5: feats GEMM (split-K, 64x64 tile, 4x4/thread) ---------
// psum[kz][n][j] = sum_{t in chunk} sum_h hs[n][t][h] * W1[j][t*128+h]
__global__ void __launch_bounds__(256) k_feats(const float* __restrict__ W1) {
    __shared__ __align__(16) float sh_hs[TM][HH + 4];     // padded rows
    __shared__ __align__(16) float sh_w[NINTER][HH + 4];

    int tile = blockIdx.x;        // 0..19
    int kz = blockIdx.y;          // 0..13
    int tid = threadIdx.x;
    int rr = tid & 15;            // rows rr, rr+16, rr+32, rr+48
    int j0 = (tid >> 4) * 4;      // 4 inter cols
    u64 a[4][4];
    #pragma unroll
    for (int r = 0; r < 4; r++)
        #pragma unroll
        for (int c = 0; c < 4; c++) a[r][c] = 0;

    int t0 = kz * TCHUNK;
    for (int tt = 0; tt < TCHUNK; tt++) {
        int t = t0 + tt;
        __syncthreads();
        for (int i = tid; i < TM * 32; i += 256) {
            int s = i >> 5, kq = i & 31;
            ((float4*)&sh_hs[s][0])[kq] =
                ((const float4*)(g_hs + ((size_t)(tile * TM + s) * TT + t) * HH))[kq];
        }
        for (int i = tid; i < NINTER * 32; i += 256) {
            int j = i >> 5, kq = i & 31;
            ((float4*)&sh_w[j][0])[kq] =
                ((const float4*)(W1 + (size_t)j * (TT * HH) + (size_t)t * HH))[kq];
        }
        __syncthreads();
        #pragma unroll 4
        for (int kq = 0; kq < 32; kq++) {
            ulonglong2 h[4], w[4];
            #pragma unroll
            for (int r = 0; r < 4; r++)
                h[r] = ((const ulonglong2*)&sh_hs[rr + 16 * r][0])[kq];
            #pragma unroll
            for (int c = 0; c < 4; c++)
                w[c] = ((const ulonglong2*)&sh_w[j0 + c][0])[kq];
            #pragma unroll
            for (int r = 0; r < 4; r++)
                #pragma unroll
                for (int c = 0; c < 4; c++) {
                    a[r][c] = ffma2(h[r].x, w[c].x, a[r][c]);
                    a[r][c] = ffma2(h[r].y, w[c].y, a[r][c]);
                }
        }
    }
    #pragma unroll
    for (int r = 0; r < 4; r++) {
        size_t base = ((size_t)kz * NN + (tile * TM + rr + 16 * r)) * NINTER + j0;
        #pragma unroll
        for (int c = 0; c < 4; c++)
            g_psum[base + c] = f2lo(a[r][c]) + f2hi(a[r][c]);
    }
}

// ---------------- kernel 6: reduce split-K + bias + final linear -----------------
__global__ void __launch_bounds__(256) k_final(
    const float* __restrict__ b1, const float* __restrict__ W2,
    const float* __restrict__ b2, float* __restrict__ out)
{
    __shared__ float sf[SS * NINTER];   // 1280 feats for this batch
    __shared__ float r0[256], r1[256];
    int b = blockIdx.x, tid = threadIdx.x;

    for (int i = tid; i < SS * NINTER; i += 256) {
        int s = i / NINTER, j = i % NINTER;
        size_t nq = (size_t)b * SS + s;
        float v = b1[j];
        #pragma unroll
        for (int kz = 0; kz < KSPLIT; kz++)
            v += g_psum[((size_t)kz * NN + nq) * NINTER + j];
        sf[i] = v;
    }
    __syncthreads();
    float p0 = 0.f, p1 = 0.f;
    for (int i = tid; i < SS * NINTER; i += 256) {
        float f = sf[i];
        p0 += f * W2[i];
        p1 += f * W2[SS * NINTER + i];
    }
    r0[tid] = p0; r1[tid] = p1;
    __syncthreads();
    for (int off = 128; off; off >>= 1) {
        if (tid < off) { r0[tid] += r0[tid + off]; r1[tid] += r1[tid + off]; }
        __syncthreads();
    }
    if (tid == 0) {
        out[b * 2 + 0] = r0[0] + b2[0];
        out[b * 2 + 1] = r1[0] + b2[1];
    }
}

// ---------------- launch ----------------------------------------------------------
extern "C" void kernel_launch(void* const* d_in, const int* in_sizes, int n_in,
                              void* d_out, int out_size)
{
    const float* x   = (const float*)d_in[0];
    // d_in[1] = metadata (unused by the reference computation)
    const float* Wih = (const float*)d_in[2];
    const float* Whh = (const float*)d_in[3];
    const float* bih = (const float*)d_in[4];
    const float* bhh = (const float*)d_in[5];
    const float* W1  = (const float*)d_in[6];
    const float* b1  = (const float*)d_in[7];
    const float* W2  = (const float*)d_in[8];
    const float* b2  = (const float*)d_in[9];
    float* out = (float*)d_out;

    cudaFuncSetAttribute(k_lstm, cudaFuncAttributeMaxDynamicSharedMemorySize, LSTM_SMEM);

    k_lens<<<NN, 32>>>(x);
    k_sort<<<1, 256>>>();
    k_wt<<<64, 256>>>(Whh);
    k_lstm<<<NGRP, 256, LSTM_SMEM>>>(x, Wih, bih, bhh);
    k_feats<<<dim3(20, KSPLIT), 256>>>(W1);
    k_final<<<BB, 256>>>(b1, W2, b2, out);
}